// round 4
// baseline (speedup 1.0000x reference)
#include <cuda_runtime.h>
#include <cuda_bf16.h>
#include <mma.h>

using namespace nvcuda;

#define HEAD_DIM     128
#define NUM_SEQS     8
#define SEQ_LEN      512
#define Q_HEADS      16
#define TOTAL_TOKENS 4096
#define ROW_STRIDE   (Q_HEADS * HEAD_DIM)   // 2048 floats per token row

#define BM 64          // q rows per CTA
#define BN 64          // kv rows per tile
#define LDT 132        // padded leading dim for Q/K/V tiles (multiple of 4)
#define LDS 68         // padded leading dim for S tile (multiple of 4)

#define NTHREADS 256
#define SCALE 0.08838834764831845f  // 1/sqrt(128)

#define SMEM_FLOATS (3 * BM * LDT + BM * LDS)
#define SMEM_BYTES  (SMEM_FLOATS * (int)sizeof(float))

__device__ __forceinline__ void load_tile_scaled(float* dst, const float* src,
                                                 int row0, int head, float scale,
                                                 int tid) {
    // 64 rows x 128 cols, float4 per thread-iter
    #pragma unroll
    for (int i = tid; i < BM * (HEAD_DIM / 4); i += NTHREADS) {
        int r  = i >> 5;        // /32
        int c4 = i & 31;
        int gr = row0 + r;
        if (gr >= TOTAL_TOKENS) gr = TOTAL_TOKENS - 1;
        float4 vv = *(const float4*)&src[(size_t)gr * ROW_STRIDE + head * HEAD_DIM + c4 * 4];
        vv.x *= scale; vv.y *= scale; vv.z *= scale; vv.w *= scale;
        float* d = dst + r * LDT + c4 * 4;
        d[0] = vv.x; d[1] = vv.y; d[2] = vv.z; d[3] = vv.w;
    }
}

__device__ __forceinline__ void cvt_tf32_a(
    wmma::fragment<wmma::matrix_a, 16, 16, 8, wmma::precision::tf32, wmma::row_major>& f) {
    #pragma unroll
    for (int i = 0; i < f.num_elements; i++) f.x[i] = wmma::__float_to_tf32(f.x[i]);
}
template <typename FragB>
__device__ __forceinline__ void cvt_tf32_b(FragB& f) {
    #pragma unroll
    for (int i = 0; i < f.num_elements; i++) f.x[i] = wmma::__float_to_tf32(f.x[i]);
}

// Compute S = Qs @ Ks^T for this warp's (stripe, halfw) quarter, write to Ss.
__device__ __forceinline__ void compute_S(const float* Qs, const float* Ks, float* Ss,
                                          int stripe, int halfw) {
    wmma::fragment<wmma::accumulator, 16, 16, 8, float> sacc[2];
    wmma::fill_fragment(sacc[0], 0.0f);
    wmma::fill_fragment(sacc[1], 0.0f);
    #pragma unroll
    for (int ks = 0; ks < HEAD_DIM / 8; ks++) {
        wmma::fragment<wmma::matrix_a, 16, 16, 8, wmma::precision::tf32, wmma::row_major> a;
        wmma::load_matrix_sync(a, Qs + (stripe * 16) * LDT + ks * 8, LDT);
        cvt_tf32_a(a);
        #pragma unroll
        for (int nf = 0; nf < 2; nf++) {
            wmma::fragment<wmma::matrix_b, 16, 16, 8, wmma::precision::tf32, wmma::col_major> b;
            wmma::load_matrix_sync(b, Ks + (halfw * 32 + nf * 16) * LDT + ks * 8, LDT);
            cvt_tf32_b(b);
            wmma::mma_sync(sacc[nf], a, b, sacc[nf]);
        }
    }
    #pragma unroll
    for (int nf = 0; nf < 2; nf++) {
        wmma::store_matrix_sync(Ss + (stripe * 16) * LDS + halfw * 32 + nf * 16,
                                sacc[nf], LDS, wmma::mem_row_major);
    }
}

__global__ void __launch_bounds__(NTHREADS, 1)
varlen_attn_kernel(const float* __restrict__ Q, const float* __restrict__ K,
                   const float* __restrict__ V, const int* __restrict__ ntok32,
                   float* __restrict__ Out) {
    extern __shared__ float sm[];
    float* Qs = sm;                       // BM x LDT
    float* Ks = Qs + BM * LDT;            // BN x LDT
    float* Vs = Ks + BM * LDT;            // BN x LDT
    float* Ss = Vs + BM * LDT;            // BM x LDS
    __shared__ float m_sh[BM];
    __shared__ float l_sh[BM];

    const int qb = blockIdx.x;   // q tile within seq
    const int h  = blockIdx.y;   // head
    const int s  = blockIdx.z;   // seq

    // num_tokens dtype sniff: int64 little-endian positive lengths have the
    // high word (elem 1) == 0; int32 has the second length (>0) there.
    const int tstride = (ntok32[1] == 0) ? 2 : 1;

    int seq_start = 0;
    for (int i = 0; i < s; i++) seq_start += ntok32[i * tstride];
    const int seq_len = ntok32[s * tstride];
    if (qb * BM >= seq_len) return;

    const int q0 = seq_start + qb * BM;

    const int tid    = threadIdx.x;
    const int warp   = tid >> 5;
    const int stripe = warp >> 1;   // 0..3 : which 16-row stripe
    const int halfw  = warp & 1;    // 0/1  : which half of the n range

    // ---- load Q tile (pre-scaled) ----
    load_tile_scaled(Qs, Q, q0, h, SCALE, tid);
    if (tid < BM) { m_sh[tid] = -1e30f; l_sh[tid] = 0.0f; }
    __syncthreads();

    const int nkv = (seq_len + BN - 1) / BN;

    // =============== PASS 1: softmax stats (m, l) ===============
    for (int kb = 0; kb < nkv; kb++) {
        load_tile_scaled(Ks, K, seq_start + kb * BN, h, 1.0f, tid);
        __syncthreads();

        compute_S(Qs, Ks, Ss, stripe, halfw);
        __syncthreads();

        const int klen = min(BN, seq_len - kb * BN);
        {
            const int r   = tid >> 2;
            const int qtr = tid & 3;
            const float* srow = Ss + r * LDS + qtr * 16;
            float mx = -1e30f;
            #pragma unroll
            for (int j = 0; j < 16; j++) {
                if (qtr * 16 + j < klen) mx = fmaxf(mx, srow[j]);
            }
            #pragma unroll
            for (int o = 1; o < 4; o <<= 1)
                mx = fmaxf(mx, __shfl_xor_sync(0xffffffffu, mx, o));
            const float m_old = m_sh[r];
            const float m_new = fmaxf(m_old, mx);
            float sum = 0.0f;
            #pragma unroll
            for (int j = 0; j < 16; j++) {
                if (qtr * 16 + j < klen) sum += __expf(srow[j] - m_new);
            }
            #pragma unroll
            for (int o = 1; o < 4; o <<= 1)
                sum += __shfl_xor_sync(0xffffffffu, sum, o);
            if (qtr == 0) {
                l_sh[r] = l_sh[r] * __expf(m_old - m_new) + sum;
                m_sh[r] = m_new;
            }
        }
        __syncthreads();
    }

    // invert l
    if (tid < BM) l_sh[tid] = 1.0f / l_sh[tid];
    __syncthreads();

    // =============== PASS 2: O = softmax(S) @ V ===============
    wmma::fragment<wmma::accumulator, 16, 16, 8, float> oacc[4];
    #pragma unroll
    for (int nf = 0; nf < 4; nf++) wmma::fill_fragment(oacc[nf], 0.0f);

    for (int kb = 0; kb < nkv; kb++) {
        load_tile_scaled(Ks, K, seq_start + kb * BN, h, 1.0f, tid);
        load_tile_scaled(Vs, V, seq_start + kb * BN, h, 1.0f, tid);
        __syncthreads();

        compute_S(Qs, Ks, Ss, stripe, halfw);
        __syncthreads();

        const int klen = min(BN, seq_len - kb * BN);
        #pragma unroll 4
        for (int i = tid; i < BM * BN; i += NTHREADS) {
            const int r = i >> 6;
            const int j = i & 63;
            float p = 0.0f;
            if (j < klen) p = __expf(Ss[r * LDS + j] - m_sh[r]) * l_sh[r];
            Ss[r * LDS + j] = p;
        }
        __syncthreads();

        // O += P @ V : A = P (row-major, ld=LDS), B = V (row-major, ld=LDT)
        #pragma unroll
        for (int ks = 0; ks < BN / 8; ks++) {
            wmma::fragment<wmma::matrix_a, 16, 16, 8, wmma::precision::tf32, wmma::row_major> a;
            wmma::load_matrix_sync(a, Ss + (stripe * 16) * LDS + ks * 8, LDS);
            cvt_tf32_a(a);
            #pragma unroll
            for (int nf = 0; nf < 4; nf++) {
                wmma::fragment<wmma::matrix_b, 16, 16, 8, wmma::precision::tf32, wmma::row_major> b;
                wmma::load_matrix_sync(b, Vs + (ks * 8) * LDT + halfw * 64 + nf * 16, LDT);
                cvt_tf32_b(b);
                wmma::mma_sync(oacc[nf], a, b, oacc[nf]);
            }
        }
        __syncthreads();
    }

    // ---- store O: out[h][t][d], t stride = HEAD_DIM ----
    float* op = Out + ((size_t)h * TOTAL_TOKENS + (size_t)(q0 + stripe * 16)) * HEAD_DIM
                    + halfw * 64;
    #pragma unroll
    for (int nf = 0; nf < 4; nf++) {
        wmma::store_matrix_sync(op + nf * 16, oacc[nf], HEAD_DIM, wmma::mem_row_major);
    }
}

extern "C" void kernel_launch(void* const* d_in, const int* in_sizes, int n_in,
                              void* d_out, int out_size) {
    const float* Q = (const float*)d_in[0];
    const float* K = (const float*)d_in[1];
    const float* V = (const float*)d_in[2];
    const int* ntok = (const int*)d_in[3];
    float* Out = (float*)d_out;

    cudaFuncSetAttribute(varlen_attn_kernel,
                         cudaFuncAttributeMaxDynamicSharedMemorySize, SMEM_BYTES);

    dim3 grid(SEQ_LEN / BM, Q_HEADS, NUM_SEQS);
    varlen_attn_kernel<<<grid, NTHREADS, SMEM_BYTES>>>(Q, K, V, ntok, Out);
}

// round 6
// speedup vs baseline: 3.9997x; 3.9997x over previous
#include <cuda_runtime.h>

#define HEAD_DIM     128
#define NUM_SEQS     8
#define SEQ_LEN      512
#define Q_HEADS      16
#define TOTAL_TOKENS 4096
#define ROW_STRIDE   (Q_HEADS * HEAD_DIM)   // 2048 floats per token row

#define BM 128        // q rows per CTA (8 warps x 16 rows)
#define BN 32         // kv rows per tile
#define NWARPS 8
#define NT 256
#define LDK 132       // K tile leading dim (floats): conflict-free for QK B-frags
#define LDV 136       // V tile leading dim (floats): conflict-free for PV B-frags

// (1/sqrt(128)) * log2(e): fold softmax scale + exp->exp2 conversion into Q
#define SCALE_LOG2E 0.12751744467105866f

#define SMEM_FLOATS (2 * BN * LDK + 2 * BN * LDV)
#define SMEM_BYTES  (SMEM_FLOATS * (int)sizeof(float))

__device__ __forceinline__ void cp16(float* dst_smem, const float* src) {
    unsigned sa = (unsigned)__cvta_generic_to_shared(dst_smem);
    asm volatile("cp.async.cg.shared.global [%0], [%1], 16;\n" :: "r"(sa), "l"(src));
}

__device__ __forceinline__ float ex2f(float x) {
    float y; asm("ex2.approx.f32 %0, %1;" : "=f"(y) : "f"(x)); return y;
}

// round-to-nearest fp32 -> tf32 (matches wmma::__float_to_tf32; avoids the
// biased truncation the MMA HW applies to raw fp32 bits)
__device__ __forceinline__ unsigned f2tf32(float x) {
    unsigned y; asm("cvt.rna.tf32.f32 %0, %1;" : "=r"(y) : "f"(x)); return y;
}

// D += A(16x8 tf32, row) * B(8x8 tf32, col)
__device__ __forceinline__ void mma_tf32(float* d, const unsigned* a, const unsigned* b) {
    asm volatile(
        "mma.sync.aligned.m16n8k8.row.col.f32.tf32.tf32.f32 "
        "{%0,%1,%2,%3}, {%4,%5,%6,%7}, {%8,%9}, {%0,%1,%2,%3};\n"
        : "+f"(d[0]), "+f"(d[1]), "+f"(d[2]), "+f"(d[3])
        : "r"(a[0]), "r"(a[1]), "r"(a[2]), "r"(a[3]), "r"(b[0]), "r"(b[1]));
}

__device__ __forceinline__ void load_kv_async(float* dK, float* dV,
                                              const float* K, const float* V,
                                              int row0, int head, int tid) {
    // BN(32) rows x 32 chunks of 16B per tensor; 256 threads -> 4 iters each
    #pragma unroll
    for (int i = 0; i < 4; i++) {
        int idx = tid + i * NT;
        int r = idx >> 5, c = idx & 31;
        int gr = row0 + r; if (gr >= TOTAL_TOKENS) gr = TOTAL_TOKENS - 1;
        cp16(dK + r * LDK + c * 4, K + (size_t)gr * ROW_STRIDE + head * HEAD_DIM + c * 4);
    }
    #pragma unroll
    for (int i = 0; i < 4; i++) {
        int idx = tid + i * NT;
        int r = idx >> 5, c = idx & 31;
        int gr = row0 + r; if (gr >= TOTAL_TOKENS) gr = TOTAL_TOKENS - 1;
        cp16(dV + r * LDV + c * 4, V + (size_t)gr * ROW_STRIDE + head * HEAD_DIM + c * 4);
    }
}

__global__ void __launch_bounds__(NT, 1)
fa_kernel(const float* __restrict__ Q, const float* __restrict__ K,
          const float* __restrict__ V, const int* __restrict__ ntok,
          float* __restrict__ Out) {
    extern __shared__ float smbuf[];
    float* KsA = smbuf;
    float* KsB = smbuf + BN * LDK;
    float* VsA = smbuf + 2 * BN * LDK;
    float* VsB = VsA + BN * LDV;

    const int qb = blockIdx.x, h = blockIdx.y, s = blockIdx.z;

    // num_tokens dtype sniff: int64 LE positive lengths have high word == 0
    const int tstr = (ntok[1] == 0) ? 2 : 1;
    int seq_start = 0;
    for (int i = 0; i < s; i++) seq_start += ntok[i * tstr];
    const int seq_len = ntok[s * tstr];
    if (qb * BM >= seq_len) return;
    const int q0 = seq_start + qb * BM;

    const int tid = threadIdx.x;
    const int w = tid >> 5, lane = tid & 31;
    const int qr = lane >> 2;   // row-in-8 within fragment
    const int qc = lane & 3;    // col group

    // ---- stage Q (scaled by SCALE*log2e) through smem into A-fragments ----
    unsigned qa[16][4];
    for (int st = 0; st < 4; st++) {
        for (int i = tid; i < 32 * 32; i += NT) {
            int r = i >> 5, c4 = i & 31;
            int gr = q0 + st * 32 + r; if (gr >= TOTAL_TOKENS) gr = TOTAL_TOKENS - 1;
            float4 vv = *(const float4*)&Q[(size_t)gr * ROW_STRIDE + h * HEAD_DIM + c4 * 4];
            float* d = KsA + r * LDK + c4 * 4;
            d[0] = vv.x * SCALE_LOG2E; d[1] = vv.y * SCALE_LOG2E;
            d[2] = vv.z * SCALE_LOG2E; d[3] = vv.w * SCALE_LOG2E;
        }
        __syncthreads();
        if ((w >> 1) == st) {
            int lr = (w & 1) * 16;
            #pragma unroll
            for (int kc = 0; kc < 16; kc++) {
                const float* base = KsA + (lr + qr) * LDK + kc * 8 + qc;
                qa[kc][0] = f2tf32(base[0]);
                qa[kc][1] = f2tf32(base[8 * LDK]);
                qa[kc][2] = f2tf32(base[4]);
                qa[kc][3] = f2tf32(base[8 * LDK + 4]);
            }
        }
        __syncthreads();
    }

    float o[16][4];
    #pragma unroll
    for (int nc = 0; nc < 16; nc++) { o[nc][0] = o[nc][1] = o[nc][2] = o[nc][3] = 0.f; }
    float m0 = -1e30f, m1 = -1e30f, l0 = 0.f, l1 = 0.f;

    const int nkv = (seq_len + BN - 1) / BN;

    load_kv_async(KsA, VsA, K, V, seq_start, h, tid);
    asm volatile("cp.async.commit_group;\n");

    for (int kb = 0; kb < nkv; kb++) {
        const int cur = kb & 1;
        float* Kt = cur ? KsB : KsA;
        float* Vt = cur ? VsB : VsA;

        if (kb + 1 < nkv) {
            load_kv_async(cur ? KsA : KsB, cur ? VsA : VsB, K, V,
                          seq_start + (kb + 1) * BN, h, tid);
            asm volatile("cp.async.commit_group;\n");
            asm volatile("cp.async.wait_group 1;\n");
        } else {
            asm volatile("cp.async.wait_group 0;\n");
        }
        __syncthreads();

        // ---- S = Q K^T (4 n-chunks of 8) ----
        float sfr[4][4];
        #pragma unroll
        for (int nc = 0; nc < 4; nc++) {
            sfr[nc][0] = sfr[nc][1] = sfr[nc][2] = sfr[nc][3] = 0.f;
            #pragma unroll
            for (int kc = 0; kc < 16; kc++) {
                unsigned b[2];
                const float* bb = Kt + (nc * 8 + qr) * LDK + kc * 8 + qc;
                b[0] = f2tf32(bb[0]);
                b[1] = f2tf32(bb[4]);
                mma_tf32(sfr[nc], qa[kc], b);
            }
        }

        // mask tail (klen < BN)
        const int klen = min(BN, seq_len - kb * BN);
        if (klen < BN) {
            #pragma unroll
            for (int nc = 0; nc < 4; nc++) {
                int c0 = nc * 8 + 2 * qc;
                if (c0 >= klen)     { sfr[nc][0] = -1e30f; sfr[nc][2] = -1e30f; }
                if (c0 + 1 >= klen) { sfr[nc][1] = -1e30f; sfr[nc][3] = -1e30f; }
            }
        }

        // ---- online softmax (log2 domain) ----
        float mx0 = -1e30f, mx1 = -1e30f;
        #pragma unroll
        for (int nc = 0; nc < 4; nc++) {
            mx0 = fmaxf(mx0, fmaxf(sfr[nc][0], sfr[nc][1]));
            mx1 = fmaxf(mx1, fmaxf(sfr[nc][2], sfr[nc][3]));
        }
        mx0 = fmaxf(mx0, __shfl_xor_sync(0xffffffffu, mx0, 1));
        mx0 = fmaxf(mx0, __shfl_xor_sync(0xffffffffu, mx0, 2));
        mx1 = fmaxf(mx1, __shfl_xor_sync(0xffffffffu, mx1, 1));
        mx1 = fmaxf(mx1, __shfl_xor_sync(0xffffffffu, mx1, 2));
        const float mn0 = fmaxf(m0, mx0), mn1 = fmaxf(m1, mx1);
        const float f0 = ex2f(m0 - mn0), f1 = ex2f(m1 - mn1);
        m0 = mn0; m1 = mn1;

        float sum0 = 0.f, sum1 = 0.f;
        #pragma unroll
        for (int nc = 0; nc < 4; nc++) {
            sfr[nc][0] = ex2f(sfr[nc][0] - mn0);
            sfr[nc][1] = ex2f(sfr[nc][1] - mn0);
            sfr[nc][2] = ex2f(sfr[nc][2] - mn1);
            sfr[nc][3] = ex2f(sfr[nc][3] - mn1);
            sum0 += sfr[nc][0] + sfr[nc][1];
            sum1 += sfr[nc][2] + sfr[nc][3];
        }
        sum0 += __shfl_xor_sync(0xffffffffu, sum0, 1);
        sum0 += __shfl_xor_sync(0xffffffffu, sum0, 2);
        sum1 += __shfl_xor_sync(0xffffffffu, sum1, 1);
        sum1 += __shfl_xor_sync(0xffffffffu, sum1, 2);
        l0 = l0 * f0 + sum0;
        l1 = l1 * f1 + sum1;

        #pragma unroll
        for (int nc = 0; nc < 16; nc++) {
            o[nc][0] *= f0; o[nc][1] *= f0; o[nc][2] *= f1; o[nc][3] *= f1;
        }

        // ---- P: C-fragment layout -> A-fragment layout (warp shuffles) ----
        unsigned pa[4][4];
        const int srcA = (lane & ~3) | (qc >> 1);
        const int srcB = srcA | 2;
        const bool odd = qc & 1;
        #pragma unroll
        for (int nc = 0; nc < 4; nc++) {
            float c0 = sfr[nc][0], c1 = sfr[nc][1], c2 = sfr[nc][2], c3 = sfr[nc][3];
            float u0 = __shfl_sync(0xffffffffu, c0, srcA);
            float u1 = __shfl_sync(0xffffffffu, c1, srcA);
            float u2 = __shfl_sync(0xffffffffu, c2, srcA);
            float u3 = __shfl_sync(0xffffffffu, c3, srcA);
            float v0 = __shfl_sync(0xffffffffu, c0, srcB);
            float v1 = __shfl_sync(0xffffffffu, c1, srcB);
            float v2 = __shfl_sync(0xffffffffu, c2, srcB);
            float v3 = __shfl_sync(0xffffffffu, c3, srcB);
            pa[nc][0] = f2tf32(odd ? u1 : u0);
            pa[nc][1] = f2tf32(odd ? u3 : u2);
            pa[nc][2] = f2tf32(odd ? v1 : v0);
            pa[nc][3] = f2tf32(odd ? v3 : v2);
        }

        // ---- O += P V (16 n-chunks x 4 k-chunks) ----
        #pragma unroll
        for (int nc = 0; nc < 16; nc++) {
            #pragma unroll
            for (int kc = 0; kc < 4; kc++) {
                unsigned b[2];
                const float* bb = Vt + (kc * 8 + qc) * LDV + nc * 8 + qr;
                b[0] = f2tf32(bb[0]);
                b[1] = f2tf32(bb[4 * LDV]);
                mma_tf32(o[nc], pa[kc], b);
            }
        }
        __syncthreads();
    }

    // ---- epilogue: normalize by 1/l and store ----
    const float r0 = 1.f / l0, r1 = 1.f / l1;
    const int row0g = q0 + w * 16 + qr;
    const int row1g = row0g + 8;
    const int lim = seq_start + seq_len;
    #pragma unroll
    for (int nc = 0; nc < 16; nc++) {
        if (row0g < lim) {
            float2 val = make_float2(o[nc][0] * r0, o[nc][1] * r0);
            *(float2*)&Out[((size_t)h * TOTAL_TOKENS + row0g) * HEAD_DIM + nc * 8 + 2 * qc] = val;
        }
        if (row1g < lim) {
            float2 val = make_float2(o[nc][2] * r1, o[nc][3] * r1);
            *(float2*)&Out[((size_t)h * TOTAL_TOKENS + row1g) * HEAD_DIM + nc * 8 + 2 * qc] = val;
        }
    }
}

extern "C" void kernel_launch(void* const* d_in, const int* in_sizes, int n_in,
                              void* d_out, int out_size) {
    const float* Q = (const float*)d_in[0];
    const float* K = (const float*)d_in[1];
    const float* V = (const float*)d_in[2];
    const int* ntok = (const int*)d_in[3];
    float* Out = (float*)d_out;

    cudaFuncSetAttribute(fa_kernel,
                         cudaFuncAttributeMaxDynamicSharedMemorySize, SMEM_BYTES);

    dim3 grid(SEQ_LEN / BM, Q_HEADS, NUM_SEQS);   // 4 x 16 x 8 = 512 CTAs
    fa_kernel<<<grid, NT, SMEM_BYTES>>>(Q, K, V, ntok, Out);
}

// round 7
// speedup vs baseline: 4.0015x; 1.0005x over previous
#include <cuda_runtime.h>

#define HEAD_DIM     128
#define NUM_SEQS     8
#define SEQ_LEN      512
#define Q_HEADS      16
#define TOTAL_TOKENS 4096
#define ROW_STRIDE   (Q_HEADS * HEAD_DIM)   // 2048 floats per token row

#define BM 128        // q rows per CTA (8 warps x 16 rows)
#define BN 32         // kv rows per tile
#define NWARPS 8
#define NT 256
#define LDK 132       // K tile leading dim (floats): conflict-free for QK B-frags
#define LDV 136       // V tile leading dim (floats): conflict-free for PV B-frags

// (1/sqrt(128)) * log2(e): fold softmax scale + exp->exp2 conversion into Q
#define SCALE_LOG2E 0.12751744467105866f

#define SMEM_FLOATS (2 * BN * LDK + 2 * BN * LDV)
#define SMEM_BYTES  (SMEM_FLOATS * (int)sizeof(float))

__device__ __forceinline__ void cp16(float* dst_smem, const float* src) {
    unsigned sa = (unsigned)__cvta_generic_to_shared(dst_smem);
    asm volatile("cp.async.cg.shared.global [%0], [%1], 16;\n" :: "r"(sa), "l"(src));
}

__device__ __forceinline__ float ex2f(float x) {
    float y; asm("ex2.approx.f32 %0, %1;" : "=f"(y) : "f"(x)); return y;
}

// round-to-nearest fp32 -> tf32 (matches wmma::__float_to_tf32; avoids the
// biased truncation the MMA HW applies to raw fp32 bits)
__device__ __forceinline__ unsigned f2tf32(float x) {
    unsigned y; asm("cvt.rna.tf32.f32 %0, %1;" : "=r"(y) : "f"(x)); return y;
}

// D += A(16x8 tf32, row) * B(8x8 tf32, col)
__device__ __forceinline__ void mma_tf32(float* d, const unsigned* a, const unsigned* b) {
    asm volatile(
        "mma.sync.aligned.m16n8k8.row.col.f32.tf32.tf32.f32 "
        "{%0,%1,%2,%3}, {%4,%5,%6,%7}, {%8,%9}, {%0,%1,%2,%3};\n"
        : "+f"(d[0]), "+f"(d[1]), "+f"(d[2]), "+f"(d[3])
        : "r"(a[0]), "r"(a[1]), "r"(a[2]), "r"(a[3]), "r"(b[0]), "r"(b[1]));
}

__device__ __forceinline__ void load_kv_async(float* dK, float* dV,
                                              const float* K, const float* V,
                                              int row0, int head, int tid) {
    // BN(32) rows x 32 chunks of 16B per tensor; 256 threads -> 4 iters each
    #pragma unroll
    for (int i = 0; i < 4; i++) {
        int idx = tid + i * NT;
        int r = idx >> 5, c = idx & 31;
        int gr = row0 + r; if (gr >= TOTAL_TOKENS) gr = TOTAL_TOKENS - 1;
        cp16(dK + r * LDK + c * 4, K + (size_t)gr * ROW_STRIDE + head * HEAD_DIM + c * 4);
    }
    #pragma unroll
    for (int i = 0; i < 4; i++) {
        int idx = tid + i * NT;
        int r = idx >> 5, c = idx & 31;
        int gr = row0 + r; if (gr >= TOTAL_TOKENS) gr = TOTAL_TOKENS - 1;
        cp16(dV + r * LDV + c * 4, V + (size_t)gr * ROW_STRIDE + head * HEAD_DIM + c * 4);
    }
}

__global__ void __launch_bounds__(NT, 1)
fa_kernel(const float* __restrict__ Q, const float* __restrict__ K,
          const float* __restrict__ V, const int* __restrict__ ntok,
          float* __restrict__ Out) {
    extern __shared__ float smbuf[];
    float* KsA = smbuf;
    float* KsB = smbuf + BN * LDK;
    float* VsA = smbuf + 2 * BN * LDK;
    float* VsB = VsA + BN * LDV;

    const int qb = blockIdx.x, h = blockIdx.y, s = blockIdx.z;

    // num_tokens dtype sniff: int64 LE positive lengths have high word == 0
    const int tstr = (ntok[1] == 0) ? 2 : 1;
    int seq_start = 0;
    for (int i = 0; i < s; i++) seq_start += ntok[i * tstr];
    const int seq_len = ntok[s * tstr];
    if (qb * BM >= seq_len) return;
    const int q0 = seq_start + qb * BM;

    const int tid = threadIdx.x;
    const int w = tid >> 5, lane = tid & 31;
    const int qr = lane >> 2;   // row-in-8 within fragment
    const int qc = lane & 3;    // col group

    // ---- stage Q (scaled by SCALE*log2e) through smem into A-fragments ----
    unsigned qa[16][4];
    for (int st = 0; st < 4; st++) {
        for (int i = tid; i < 32 * 32; i += NT) {
            int r = i >> 5, c4 = i & 31;
            int gr = q0 + st * 32 + r; if (gr >= TOTAL_TOKENS) gr = TOTAL_TOKENS - 1;
            float4 vv = *(const float4*)&Q[(size_t)gr * ROW_STRIDE + h * HEAD_DIM + c4 * 4];
            float* d = KsA + r * LDK + c4 * 4;
            d[0] = vv.x * SCALE_LOG2E; d[1] = vv.y * SCALE_LOG2E;
            d[2] = vv.z * SCALE_LOG2E; d[3] = vv.w * SCALE_LOG2E;
        }
        __syncthreads();
        if ((w >> 1) == st) {
            int lr = (w & 1) * 16;
            #pragma unroll
            for (int kc = 0; kc < 16; kc++) {
                const float* base = KsA + (lr + qr) * LDK + kc * 8 + qc;
                qa[kc][0] = f2tf32(base[0]);
                qa[kc][1] = f2tf32(base[8 * LDK]);
                qa[kc][2] = f2tf32(base[4]);
                qa[kc][3] = f2tf32(base[8 * LDK + 4]);
            }
        }
        __syncthreads();
    }

    float o[16][4];
    #pragma unroll
    for (int nc = 0; nc < 16; nc++) { o[nc][0] = o[nc][1] = o[nc][2] = o[nc][3] = 0.f; }
    float m0 = -1e30f, m1 = -1e30f, l0 = 0.f, l1 = 0.f;

    const int nkv = (seq_len + BN - 1) / BN;

    load_kv_async(KsA, VsA, K, V, seq_start, h, tid);
    asm volatile("cp.async.commit_group;\n");

    for (int kb = 0; kb < nkv; kb++) {
        const int cur = kb & 1;
        float* Kt = cur ? KsB : KsA;
        float* Vt = cur ? VsB : VsA;

        if (kb + 1 < nkv) {
            load_kv_async(cur ? KsA : KsB, cur ? VsA : VsB, K, V,
                          seq_start + (kb + 1) * BN, h, tid);
            asm volatile("cp.async.commit_group;\n");
            asm volatile("cp.async.wait_group 1;\n");
        } else {
            asm volatile("cp.async.wait_group 0;\n");
        }
        __syncthreads();

        // ---- S = Q K^T (4 n-chunks of 8) ----
        float sfr[4][4];
        #pragma unroll
        for (int nc = 0; nc < 4; nc++) {
            sfr[nc][0] = sfr[nc][1] = sfr[nc][2] = sfr[nc][3] = 0.f;
            #pragma unroll
            for (int kc = 0; kc < 16; kc++) {
                unsigned b[2];
                const float* bb = Kt + (nc * 8 + qr) * LDK + kc * 8 + qc;
                b[0] = f2tf32(bb[0]);
                b[1] = f2tf32(bb[4]);
                mma_tf32(sfr[nc], qa[kc], b);
            }
        }

        // mask tail (klen < BN)
        const int klen = min(BN, seq_len - kb * BN);
        if (klen < BN) {
            #pragma unroll
            for (int nc = 0; nc < 4; nc++) {
                int c0 = nc * 8 + 2 * qc;
                if (c0 >= klen)     { sfr[nc][0] = -1e30f; sfr[nc][2] = -1e30f; }
                if (c0 + 1 >= klen) { sfr[nc][1] = -1e30f; sfr[nc][3] = -1e30f; }
            }
        }

        // ---- online softmax (log2 domain) ----
        float mx0 = -1e30f, mx1 = -1e30f;
        #pragma unroll
        for (int nc = 0; nc < 4; nc++) {
            mx0 = fmaxf(mx0, fmaxf(sfr[nc][0], sfr[nc][1]));
            mx1 = fmaxf(mx1, fmaxf(sfr[nc][2], sfr[nc][3]));
        }
        mx0 = fmaxf(mx0, __shfl_xor_sync(0xffffffffu, mx0, 1));
        mx0 = fmaxf(mx0, __shfl_xor_sync(0xffffffffu, mx0, 2));
        mx1 = fmaxf(mx1, __shfl_xor_sync(0xffffffffu, mx1, 1));
        mx1 = fmaxf(mx1, __shfl_xor_sync(0xffffffffu, mx1, 2));
        const float mn0 = fmaxf(m0, mx0), mn1 = fmaxf(m1, mx1);
        const float f0 = ex2f(m0 - mn0), f1 = ex2f(m1 - mn1);
        m0 = mn0; m1 = mn1;

        float sum0 = 0.f, sum1 = 0.f;
        #pragma unroll
        for (int nc = 0; nc < 4; nc++) {
            sfr[nc][0] = ex2f(sfr[nc][0] - mn0);
            sfr[nc][1] = ex2f(sfr[nc][1] - mn0);
            sfr[nc][2] = ex2f(sfr[nc][2] - mn1);
            sfr[nc][3] = ex2f(sfr[nc][3] - mn1);
            sum0 += sfr[nc][0] + sfr[nc][1];
            sum1 += sfr[nc][2] + sfr[nc][3];
        }
        sum0 += __shfl_xor_sync(0xffffffffu, sum0, 1);
        sum0 += __shfl_xor_sync(0xffffffffu, sum0, 2);
        sum1 += __shfl_xor_sync(0xffffffffu, sum1, 1);
        sum1 += __shfl_xor_sync(0xffffffffu, sum1, 2);
        l0 = l0 * f0 + sum0;
        l1 = l1 * f1 + sum1;

        #pragma unroll
        for (int nc = 0; nc < 16; nc++) {
            o[nc][0] *= f0; o[nc][1] *= f0; o[nc][2] *= f1; o[nc][3] *= f1;
        }

        // ---- P: C-fragment layout -> A-fragment layout (warp shuffles) ----
        unsigned pa[4][4];
        const int srcA = (lane & ~3) | (qc >> 1);
        const int srcB = srcA | 2;
        const bool odd = qc & 1;
        #pragma unroll
        for (int nc = 0; nc < 4; nc++) {
            float c0 = sfr[nc][0], c1 = sfr[nc][1], c2 = sfr[nc][2], c3 = sfr[nc][3];
            float u0 = __shfl_sync(0xffffffffu, c0, srcA);
            float u1 = __shfl_sync(0xffffffffu, c1, srcA);
            float u2 = __shfl_sync(0xffffffffu, c2, srcA);
            float u3 = __shfl_sync(0xffffffffu, c3, srcA);
            float v0 = __shfl_sync(0xffffffffu, c0, srcB);
            float v1 = __shfl_sync(0xffffffffu, c1, srcB);
            float v2 = __shfl_sync(0xffffffffu, c2, srcB);
            float v3 = __shfl_sync(0xffffffffu, c3, srcB);
            pa[nc][0] = f2tf32(odd ? u1 : u0);
            pa[nc][1] = f2tf32(odd ? u3 : u2);
            pa[nc][2] = f2tf32(odd ? v1 : v0);
            pa[nc][3] = f2tf32(odd ? v3 : v2);
        }

        // ---- O += P V (16 n-chunks x 4 k-chunks) ----
        #pragma unroll
        for (int nc = 0; nc < 16; nc++) {
            #pragma unroll
            for (int kc = 0; kc < 4; kc++) {
                unsigned b[2];
                const float* bb = Vt + (kc * 8 + qc) * LDV + nc * 8 + qr;
                b[0] = f2tf32(bb[0]);
                b[1] = f2tf32(bb[4 * LDV]);
                mma_tf32(o[nc], pa[kc], b);
            }
        }
        __syncthreads();
    }

    // ---- epilogue: normalize by 1/l and store ----
    const float r0 = 1.f / l0, r1 = 1.f / l1;
    const int row0g = q0 + w * 16 + qr;
    const int row1g = row0g + 8;
    const int lim = seq_start + seq_len;
    #pragma unroll
    for (int nc = 0; nc < 16; nc++) {
        if (row0g < lim) {
            float2 val = make_float2(o[nc][0] * r0, o[nc][1] * r0);
            *(float2*)&Out[((size_t)h * TOTAL_TOKENS + row0g) * HEAD_DIM + nc * 8 + 2 * qc] = val;
        }
        if (row1g < lim) {
            float2 val = make_float2(o[nc][2] * r1, o[nc][3] * r1);
            *(float2*)&Out[((size_t)h * TOTAL_TOKENS + row1g) * HEAD_DIM + nc * 8 + 2 * qc] = val;
        }
    }
}

extern "C" void kernel_launch(void* const* d_in, const int* in_sizes, int n_in,
                              void* d_out, int out_size) {
    const float* Q = (const float*)d_in[0];
    const float* K = (const float*)d_in[1];
    const float* V = (const float*)d_in[2];
    const int* ntok = (const int*)d_in[3];
    float* Out = (float*)d_out;

    cudaFuncSetAttribute(fa_kernel,
                         cudaFuncAttributeMaxDynamicSharedMemorySize, SMEM_BYTES);

    dim3 grid(SEQ_LEN / BM, Q_HEADS, NUM_SEQS);   // 4 x 16 x 8 = 512 CTAs
    fa_kernel<<<grid, NT, SMEM_BYTES>>>(Q, K, V, ntok, Out);
}